// round 3
// baseline (speedup 1.0000x reference)
#include <cuda_runtime.h>

typedef unsigned long long u64;

// ---------------- scratch (static device globals: allocation-free) ----------------
__device__ float g_k1t[4*8*4096*16];    // [b,h,s,d] level-1 keys
__device__ float g_v1t[4*8*4096*16];
__device__ float g_k0t[4*8*16384*16];   // [b,h,s,d] level-2 keys
__device__ float g_v0t[4*8*16384*16];
__device__ float g_msg0[4*8*1024*16];         // [b,h,l,d]
__device__ float g_msg1[4*8*1024*4*16];       // [b,h,l,t,d]
__device__ float g_msg2[4*8*4096*4*16];       // [b,h,l,t,d]
__device__ int   g_idx0[4*8*1024*16];         // [b,h,l,16]
__device__ int   g_idx1[4*8*4096*8];          // [b,h,pix,8]

// ---------------- packed f32x2 helpers ----------------
__device__ __forceinline__ u64 pack2(float a, float b) {
    u64 r; asm("mov.b64 %0,{%1,%2};" : "=l"(r) : "f"(a), "f"(b)); return r;
}
__device__ __forceinline__ void unpack2(u64 v, float& a, float& b) {
    asm("mov.b64 {%0,%1},%2;" : "=f"(a), "=f"(b) : "l"(v));
}
__device__ __forceinline__ u64 ffma2(u64 a, u64 b, u64 c) {
    u64 d; asm("fma.rn.f32x2 %0,%1,%2,%3;" : "=l"(d) : "l"(a), "l"(b), "l"(c)); return d;
}
__device__ __forceinline__ u64 mul2(u64 a, u64 b) {
    u64 d; asm("mul.rn.f32x2 %0,%1,%2;" : "=l"(d) : "l"(a), "l"(b)); return d;
}
__device__ __forceinline__ u64 add2(u64 a, u64 b) {
    u64 d; asm("add.rn.f32x2 %0,%1,%2;" : "=l"(d) : "l"(a), "l"(b)); return d;
}

__device__ __forceinline__ float dot16(const u64 (&qr)[8], float4 a, float4 b, float4 c, float4 d) {
    u64 k0 = pack2(a.x,a.y), k1 = pack2(a.z,a.w);
    u64 k2 = pack2(b.x,b.y), k3 = pack2(b.z,b.w);
    u64 k4 = pack2(c.x,c.y), k5 = pack2(c.z,c.w);
    u64 k6 = pack2(d.x,d.y), k7 = pack2(d.z,d.w);
    u64 d0 = mul2(qr[0],k0), d1 = mul2(qr[1],k1), d2 = mul2(qr[2],k2), d3 = mul2(qr[3],k3);
    d0 = ffma2(qr[4],k4,d0); d1 = ffma2(qr[5],k5,d1);
    d2 = ffma2(qr[6],k6,d2); d3 = ffma2(qr[7],k7,d3);
    u64 e0 = add2(d0,d1), e1 = add2(d2,d3), e2 = add2(e0,e1);
    float lo, hi; unpack2(e2, lo, hi);
    return lo + hi;
}

__device__ __forceinline__ void acc_fma(u64 (&acc)[8], u64 e2, float4 a, float4 b, float4 c, float4 d) {
    acc[0] = ffma2(e2, pack2(a.x,a.y), acc[0]);
    acc[1] = ffma2(e2, pack2(a.z,a.w), acc[1]);
    acc[2] = ffma2(e2, pack2(b.x,b.y), acc[2]);
    acc[3] = ffma2(e2, pack2(b.z,b.w), acc[3]);
    acc[4] = ffma2(e2, pack2(c.x,c.y), acc[4]);
    acc[5] = ffma2(e2, pack2(c.z,c.w), acc[5]);
    acc[6] = ffma2(e2, pack2(d.x,d.y), acc[6]);
    acc[7] = ffma2(e2, pack2(d.z,d.w), acc[7]);
}
__device__ __forceinline__ void acc_rescale_add(u64 (&acc)[8], u64 c2, float4 a, float4 b, float4 c, float4 d) {
    acc[0] = ffma2(c2, acc[0], pack2(a.x,a.y));
    acc[1] = ffma2(c2, acc[1], pack2(a.z,a.w));
    acc[2] = ffma2(c2, acc[2], pack2(b.x,b.y));
    acc[3] = ffma2(c2, acc[3], pack2(b.z,b.w));
    acc[4] = ffma2(c2, acc[4], pack2(c.x,c.y));
    acc[5] = ffma2(c2, acc[5], pack2(c.z,c.w));
    acc[6] = ffma2(c2, acc[6], pack2(d.x,d.y));
    acc[7] = ffma2(c2, acc[7], pack2(d.z,d.w));
}

template<int K>
__device__ __forceinline__ void topk_insert(float (&tv)[K], int (&ti)[K], float sc, int id) {
    // caller guarantees sc > tv[K-1]; strict-> preserves jax lower-index-first ties
    bool done = false;
    #pragma unroll
    for (int i = K-1; i >= 1; --i) {
        if (!done) {
            if (sc > tv[i-1]) { tv[i] = tv[i-1]; ti[i] = ti[i-1]; }
            else              { tv[i] = sc; ti[i] = id; done = true; }
        }
    }
    if (!done) { tv[0] = sc; ti[0] = id; }
}

__device__ __forceinline__ void store_msg(float* mo, const u64 (&acc)[8], float inv) {
    #pragma unroll
    for (int i = 0; i < 8; ++i) {
        float lo, hi; unpack2(acc[i], lo, hi);
        mo[2*i]   = lo * inv;
        mo[2*i+1] = hi * inv;
    }
}

// ---------------- transpose: NCHW [b,128,S] -> [b,h,S,16] ----------------
__global__ __launch_bounds__(256) void k_transpose(const float* __restrict__ in, int S, int which) {
    float* out = (which == 0) ? g_k1t : (which == 1) ? g_v1t : (which == 2) ? g_k0t : g_v0t;
    __shared__ float sm[128*17];  // [sl][dd], stride 17
    const int b = blockIdx.z, h = blockIdx.y;
    const int s0 = blockIdx.x * 128;
    const int tid = threadIdx.x;
    const float* ib = in + ((size_t)(b*8 + h) * 16) * S + s0;
    #pragma unroll
    for (int k = 0; k < 8; ++k) {
        int lin = tid + k*256;
        int dd = lin >> 7, sl = lin & 127;
        sm[sl*17 + dd] = ib[dd*S + sl];
    }
    __syncthreads();
    float* ob = out + ((size_t)(b*8 + h) * S + s0) * 16;
    #pragma unroll
    for (int k = 0; k < 8; ++k) {
        int lin = tid + k*256;
        int sl = lin >> 4, dd = lin & 15;
        ob[lin] = sm[sl*17 + dd];
    }
}

// ---------------- level 0: full attention on 32x32, top-16 ----------------
__global__ __launch_bounds__(128) void k_level0(const float* __restrict__ q2,
                                                const float* __restrict__ k2,
                                                const float* __restrict__ v2) {
    const int tid = threadIdx.x;
    const int bh = blockIdx.z * 8 + blockIdx.y;
    const int s = blockIdx.x * 128 + tid;
    __shared__ float kS[128*20];   // [j][dd], stride 20 (16B aligned rows)
    __shared__ float vS[128*20];

    const float* qb = q2 + (size_t)bh * 16 * 1024;
    u64 qr[8];
    #pragma unroll
    for (int i = 0; i < 8; ++i)
        qr[i] = pack2(qb[(2*i)*1024 + s], qb[(2*i+1)*1024 + s]);

    u64 acc[8];
    #pragma unroll
    for (int i = 0; i < 8; ++i) acc[i] = pack2(0.f, 0.f);
    float m = -1e30f, Z = 0.f;
    float topv[16]; int topi[16];
    #pragma unroll
    for (int i = 0; i < 16; ++i) { topv[i] = -1e30f; topi[i] = 0; }

    const float* kb = k2 + (size_t)bh * 16 * 1024;
    const float* vb = v2 + (size_t)bh * 16 * 1024;

    for (int ch = 0; ch < 1024; ch += 128) {
        __syncthreads();
        #pragma unroll
        for (int dd = 0; dd < 16; ++dd) {
            kS[tid*20 + dd] = kb[dd*1024 + ch + tid];
            vS[tid*20 + dd] = vb[dd*1024 + ch + tid];
        }
        __syncthreads();
        #pragma unroll 4
        for (int j = 0; j < 128; ++j) {
            const float4* kp = reinterpret_cast<const float4*>(kS + j*20);
            float4 ka = kp[0], kb4 = kp[1], kc = kp[2], kd = kp[3];
            float sc = dot16(qr, ka, kb4, kc, kd) * 0.25f;
            if (sc > topv[15]) topk_insert<16>(topv, topi, sc, ch + j);
            const float4* vp = reinterpret_cast<const float4*>(vS + j*20);
            float4 va = vp[0], vb4 = vp[1], vc = vp[2], vd = vp[3];
            if (sc > m) {
                float cor = __expf(m - sc);
                m = sc;
                Z = Z * cor + 1.f;
                acc_rescale_add(acc, pack2(cor, cor), va, vb4, vc, vd);
            } else {
                float e = __expf(sc - m);
                Z += e;
                acc_fma(acc, pack2(e, e), va, vb4, vc, vd);
            }
        }
    }
    float inv = 1.f / Z;
    store_msg(g_msg0 + (size_t)(bh*1024 + s)*16, acc, inv);
    int* io = g_idx0 + (size_t)(bh*1024 + s)*16;
    #pragma unroll
    for (int w = 0; w < 16; ++w) io[w] = topi[w];
}

// ---------------- level 1: 64 gathered candidates per query, top-8 ----------------
__global__ __launch_bounds__(128) void k_level1(const float* __restrict__ q1) {
    const int tid = threadIdx.x;
    const int bh = blockIdx.z * 8 + blockIdx.y;
    const int l = blockIdx.x * 32 + (tid >> 2);
    const int t = tid & 3;
    const int ly = l >> 5, lx = l & 31;
    const int y1 = 2*ly + (t >> 1), x1 = 2*lx + (t & 1);
    const int s1 = y1*64 + x1;

    const float* qb = q1 + (size_t)bh * 16 * 4096;
    u64 qr[8];
    #pragma unroll
    for (int i = 0; i < 8; ++i)
        qr[i] = pack2(qb[(2*i)*4096 + s1], qb[(2*i+1)*4096 + s1]);

    const int* ib = g_idx0 + (size_t)(bh*1024 + l)*16;
    const float* kb = g_k1t + (size_t)bh * 4096 * 16;
    const float* vb = g_v1t + (size_t)bh * 4096 * 16;

    u64 acc[8];
    #pragma unroll
    for (int i = 0; i < 8; ++i) acc[i] = pack2(0.f, 0.f);
    float m = -1e30f, Z = 0.f;
    float topv[8]; int topi[8];
    #pragma unroll
    for (int i = 0; i < 8; ++i) { topv[i] = -1e30f; topi[i] = 0; }

    for (int w = 0; w < 16; ++w) {
        int p = ib[w];
        int py = (p >> 5) << 1, px = (p & 31) << 1;
        #pragma unroll
        for (int c = 0; c < 4; ++c) {
            int cand = (py + (c >> 1))*64 + px + (c & 1);
            const float4* kp = reinterpret_cast<const float4*>(kb + (size_t)cand*16);
            float4 ka = kp[0], kb4 = kp[1], kc = kp[2], kd = kp[3];
            float sc = dot16(qr, ka, kb4, kc, kd) * 0.25f;
            if (sc > topv[7]) topk_insert<8>(topv, topi, sc, cand);
            const float4* vp = reinterpret_cast<const float4*>(vb + (size_t)cand*16);
            float4 va = vp[0], vb4 = vp[1], vc = vp[2], vd = vp[3];
            if (sc > m) {
                float cor = __expf(m - sc);
                m = sc;
                Z = Z * cor + 1.f;
                acc_rescale_add(acc, pack2(cor, cor), va, vb4, vc, vd);
            } else {
                float e = __expf(sc - m);
                Z += e;
                acc_fma(acc, pack2(e, e), va, vb4, vc, vd);
            }
        }
    }
    float inv = 1.f / Z;
    store_msg(g_msg1 + (size_t)((bh*1024 + l)*4 + t)*16, acc, inv);
    int* io = g_idx1 + (size_t)(bh*4096 + s1)*8;
    #pragma unroll
    for (int w = 0; w < 8; ++w) io[w] = topi[w];
}

// ---------------- level 2: 32 gathered candidates per query (no top-k) ----------------
__global__ __launch_bounds__(128) void k_level2(const float* __restrict__ q0) {
    const int tid = threadIdx.x;
    const int bh = blockIdx.z * 8 + blockIdx.y;
    const int l = blockIdx.x * 32 + (tid >> 2);
    const int t = tid & 3;
    const int ly = l >> 6, lx = l & 63;
    const int y = 2*ly + (t >> 1), x = 2*lx + (t & 1);
    const int s0 = y*128 + x;

    const float* qb = q0 + (size_t)bh * 16 * 16384;
    u64 qr[8];
    #pragma unroll
    for (int i = 0; i < 8; ++i)
        qr[i] = pack2(qb[(2*i)*16384 + s0], qb[(2*i+1)*16384 + s0]);

    const int* ib = g_idx1 + (size_t)(bh*4096 + l)*8;
    const float* kb = g_k0t + (size_t)bh * 16384 * 16;
    const float* vb = g_v0t + (size_t)bh * 16384 * 16;

    u64 acc[8];
    #pragma unroll
    for (int i = 0; i < 8; ++i) acc[i] = pack2(0.f, 0.f);
    float m = -1e30f, Z = 0.f;

    for (int w = 0; w < 8; ++w) {
        int p = ib[w];
        int py = (p >> 6) << 1, px = (p & 63) << 1;
        #pragma unroll
        for (int c = 0; c < 4; ++c) {
            int cand = (py + (c >> 1))*128 + px + (c & 1);
            const float4* kp = reinterpret_cast<const float4*>(kb + (size_t)cand*16);
            float4 ka = kp[0], kb4 = kp[1], kc = kp[2], kd = kp[3];
            float sc = dot16(qr, ka, kb4, kc, kd) * 0.25f;
            const float4* vp = reinterpret_cast<const float4*>(vb + (size_t)cand*16);
            float4 va = vp[0], vb4 = vp[1], vc = vp[2], vd = vp[3];
            if (sc > m) {
                float cor = __expf(m - sc);
                m = sc;
                Z = Z * cor + 1.f;
                acc_rescale_add(acc, pack2(cor, cor), va, vb4, vc, vd);
            } else {
                float e = __expf(sc - m);
                Z += e;
                acc_fma(acc, pack2(e, e), va, vb4, vc, vd);
            }
        }
    }
    float inv = 1.f / Z;
    store_msg(g_msg2 + (size_t)((bh*4096 + l)*4 + t)*16, acc, inv);
}

// ---------------- combine: weighted pyramid sum ----------------
__global__ __launch_bounds__(256) void k_combine(const float* __restrict__ wt, float* __restrict__ out) {
    const int gid = blockIdx.x * 256 + threadIdx.x;  // (b, s, h)
    float w0r = wt[0], w1r = wt[1], w2r = wt[2];
    float mx = fmaxf(w0r, fmaxf(w1r, w2r));
    float e0 = expf(w0r - mx), e1 = expf(w1r - mx), e2 = expf(w2r - mx);
    float inv = 1.f / (e0 + e1 + e2);
    float w0 = e0*inv, w1 = e1*inv, w2 = e2*inv;

    const int h = gid & 7;
    const int s = (gid >> 3) & 16383;
    const int b = gid >> 17;
    const int y = s >> 7, x = s & 127;
    const int bh = b*8 + h;
    const int l0 = (y >> 2)*32 + (x >> 2);
    const int t1 = (((y >> 1) & 1) << 1) | ((x >> 1) & 1);
    const int l2 = (y >> 1)*64 + (x >> 1);
    const int t2 = ((y & 1) << 1) | (x & 1);

    const float4* p0 = reinterpret_cast<const float4*>(g_msg0 + (size_t)(bh*1024 + l0)*16);
    const float4* p1 = reinterpret_cast<const float4*>(g_msg1 + (size_t)((bh*1024 + l0)*4 + t1)*16);
    const float4* p2 = reinterpret_cast<const float4*>(g_msg2 + (size_t)((bh*4096 + l2)*4 + t2)*16);
    float4* po = reinterpret_cast<float4*>(out + (size_t)gid*16);
    #pragma unroll
    for (int i = 0; i < 4; ++i) {
        float4 a = p0[i], c = p1[i], d = p2[i];
        float4 r;
        r.x = w0*a.x + w1*c.x + w2*d.x;
        r.y = w0*a.y + w1*c.y + w2*d.y;
        r.z = w0*a.z + w1*c.z + w2*d.z;
        r.w = w0*a.w + w1*c.w + w2*d.w;
        po[i] = r;
    }
}

// ---------------- launcher ----------------
extern "C" void kernel_launch(void* const* d_in, const int* in_sizes, int n_in,
                              void* d_out, int out_size) {
    (void)in_sizes; (void)n_in; (void)out_size;
    const float* q0 = (const float*)d_in[0];
    const float* q1 = (const float*)d_in[1];
    const float* q2 = (const float*)d_in[2];
    const float* k0 = (const float*)d_in[3];
    const float* k1 = (const float*)d_in[4];
    const float* k2 = (const float*)d_in[5];
    const float* v0 = (const float*)d_in[6];
    const float* v1 = (const float*)d_in[7];
    const float* v2 = (const float*)d_in[8];
    const float* wt = (const float*)d_in[9];
    float* out = (float*)d_out;

    k_transpose<<<dim3(32, 8, 4), 256>>>(k1, 4096, 0);
    k_transpose<<<dim3(32, 8, 4), 256>>>(v1, 4096, 1);
    k_transpose<<<dim3(128, 8, 4), 256>>>(k0, 16384, 2);
    k_transpose<<<dim3(128, 8, 4), 256>>>(v0, 16384, 3);
    k_level0<<<dim3(8, 8, 4), 128>>>(q2, k2, v2);
    k_level1<<<dim3(32, 8, 4), 128>>>(q1);
    k_level2<<<dim3(128, 8, 4), 128>>>(q0);
    k_combine<<<2048, 256>>>(wt, out);
}